// round 8
// baseline (speedup 1.0000x reference)
#include <cuda_runtime.h>
#include <cuda_fp16.h>

#define GSZ 64
#define NTILE (GSZ * GSZ * GSZ)   // 262144 tiles

// All-origins tile buffer: tile (z, y0, x0) holds the 4x4 (y,x) patch of
// cells (z, y0..y0+3, x0..x0+3), 4 channels, fp16 -> 16 cells * 8B = 128B
// = one cache line. 32 MB (L2-resident).
// uint4 j (j=0..7) holds cells 2j, 2j+1 (cell index c = dy*4+dx).
// Cell = {half2(ch0,ch1), half2(ch2,ch3)}.
__device__ uint4 g_tiles[NTILE * 8];

// ---------------------------------------------------------------------------
// Prep: one thread per (tile, dy). Tiles with x0>60 or y0>60 are never read
// by k_main (base indices clamped to [1,61] there), so clamp only the READ
// base; contents just need to be deterministic.
// ---------------------------------------------------------------------------
__global__ void __launch_bounds__(256) k_prep(const float* __restrict__ knots)
{
    int tid = blockIdx.x * 256 + threadIdx.x;     // NTILE*4 threads
    int t  = tid >> 2;
    int dy = tid & 3;
    if (t >= NTILE) return;

    int z  = t >> 12;
    int y0 = (t >> 6) & 63;
    int x0 = t & 63;
    int y  = min(y0, GSZ - 4) + dy;     // in-bounds
    int xc = min(x0, GSZ - 4);          // contiguous 64B read

    const float4* src = reinterpret_cast<const float4*>(knots)
                      + (z * GSZ + y) * GSZ + xc;

    float4 k0 = __ldg(src + 0);
    float4 k1 = __ldg(src + 1);
    float4 k2 = __ldg(src + 2);
    float4 k3 = __ldg(src + 3);

    uint4 o0, o1;
    __half2 h;
    h = __floats2half2_rn(k0.x, k0.y); o0.x = *reinterpret_cast<unsigned*>(&h);
    h = __floats2half2_rn(k0.z, k0.w); o0.y = *reinterpret_cast<unsigned*>(&h);
    h = __floats2half2_rn(k1.x, k1.y); o0.z = *reinterpret_cast<unsigned*>(&h);
    h = __floats2half2_rn(k1.z, k1.w); o0.w = *reinterpret_cast<unsigned*>(&h);
    h = __floats2half2_rn(k2.x, k2.y); o1.x = *reinterpret_cast<unsigned*>(&h);
    h = __floats2half2_rn(k2.z, k2.w); o1.y = *reinterpret_cast<unsigned*>(&h);
    h = __floats2half2_rn(k3.x, k3.y); o1.z = *reinterpret_cast<unsigned*>(&h);
    h = __floats2half2_rn(k3.z, k3.w); o1.w = *reinterpret_cast<unsigned*>(&h);

    g_tiles[t * 8 + dy * 2 + 0] = o0;
    g_tiles[t * 8 + dy * 2 + 1] = o1;
}

// ---------------------------------------------------------------------------
// Main: PAIR mapping. 2 lanes per point; lane lx in {0,1} owns y-rows
// 2lx, 2lx+1 and issues TWO LDG.256 per z -> 8 independent loads in flight
// per lane (MLP=8) without duplicating per-point state across 4 lanes.
// Per z per point the warp still touches 16 lines / 1024B per instruction
// -> 4 L1 wavefronts per point total.
// x-dot and y-combine in fp16; z-accumulate in f32. Pair-reduce (1 shfl step).
// ---------------------------------------------------------------------------
__global__ void __launch_bounds__(128) k_main(const float* __restrict__ coords,
                                              float* __restrict__ out,
                                              int n)
{
    int tid = blockIdx.x * 128 + threadIdx.x;
    int p  = tid >> 1;       // point index
    int lx = tid & 1;        // half-pair: owns y-rows 2lx, 2lx+1
    if (p >= n) return;

    float zc = __ldg(&coords[p * 3 + 0]);
    float yc = __ldg(&coords[p * 3 + 1]);
    float xc = __ldg(&coords[p * 3 + 2]);

    float fz = floorf(zc), fy = floorf(yc), fx = floorf(xc);
    int iz = (int)fz, iy = (int)fy, ix = (int)fx;
    float sz = zc - fz, sy = yc - fy, sx = xc - fx;
    iz = min(max(iz, 1), GSZ - 3);
    iy = min(max(iy, 1), GSZ - 3);
    ix = min(max(ix, 1), GSZ - 3);

    // z basis (f32, all 4 taps)
    float czv[4];
    czv[0] = sz * (-0.5f + sz * (1.0f - 0.5f * sz));
    czv[1] = 1.0f + sz * sz * (-2.5f + 1.5f * sz);
    czv[2] = sz * (0.5f + sz * (2.0f - 1.5f * sz));
    czv[3] = sz * sz * (0.5f * sz - 0.5f);

    // y basis: this lane needs taps 2lx, 2lx+1 (as broadcast half2)
    __half2 hyA, hyB;
    {
        float c0 = sy * (-0.5f + sy * (1.0f - 0.5f * sy));
        float c1 = 1.0f + sy * sy * (-2.5f + 1.5f * sy);
        float c2 = sy * (0.5f + sy * (2.0f - 1.5f * sy));
        float c3 = sy * sy * (0.5f * sy - 0.5f);
        hyA = __float2half2_rn(lx ? c2 : c0);
        hyB = __float2half2_rn(lx ? c3 : c1);
    }

    // x basis: all 4 taps as broadcast half2
    __half2 hx0, hx1, hx2, hx3;
    {
        float c0 = sx * (-0.5f + sx * (1.0f - 0.5f * sx));
        float c1 = 1.0f + sx * sx * (-2.5f + 1.5f * sx);
        float c2 = sx * (0.5f + sx * (2.0f - 1.5f * sx));
        float c3 = sx * sx * (0.5f * sx - 0.5f);
        hx0 = __float2half2_rn(c0);
        hx1 = __float2half2_rn(c1);
        hx2 = __float2half2_rn(c2);
        hx3 = __float2half2_rn(c3);
    }

    // lane's 64B slice (y-rows 2lx, 2lx+1) of tile (z, iy-1, ix-1)
    const uint4* tbase = g_tiles
        + (size_t)(((iz - 1) * GSZ + (iy - 1)) * GSZ + (ix - 1)) * 8 + lx * 4;

    float a0 = 0.f, a1 = 0.f, a2 = 0.f, a3 = 0.f;

#pragma unroll
    for (int zi = 0; zi < 4; zi++) {
        const unsigned* tpA = reinterpret_cast<const unsigned*>(
            tbase + (size_t)zi * (GSZ * GSZ * 8));
        const unsigned* tpB = tpA + 8;   // +2 uint4 = next y-row

        unsigned A0, A1, A2, A3, A4, A5, A6, A7;
        unsigned B0, B1, B2, B3, B4, B5, B6, B7;
        asm("ld.global.nc.v8.b32 {%0,%1,%2,%3,%4,%5,%6,%7}, [%8];"
            : "=r"(A0), "=r"(A1), "=r"(A2), "=r"(A3),
              "=r"(A4), "=r"(A5), "=r"(A6), "=r"(A7)
            : "l"(tpA));
        asm("ld.global.nc.v8.b32 {%0,%1,%2,%3,%4,%5,%6,%7}, [%8];"
            : "=r"(B0), "=r"(B1), "=r"(B2), "=r"(B3),
              "=r"(B4), "=r"(B5), "=r"(B6), "=r"(B7)
            : "l"(tpB));

        // x-dot row A (y-row 2lx): cells dx=0..3, ch01 / ch23
        __half2 dA01 = __hmul2(hx0, *reinterpret_cast<__half2*>(&A0));
        dA01 = __hfma2(hx1, *reinterpret_cast<__half2*>(&A2), dA01);
        dA01 = __hfma2(hx2, *reinterpret_cast<__half2*>(&A4), dA01);
        dA01 = __hfma2(hx3, *reinterpret_cast<__half2*>(&A6), dA01);
        __half2 dA23 = __hmul2(hx0, *reinterpret_cast<__half2*>(&A1));
        dA23 = __hfma2(hx1, *reinterpret_cast<__half2*>(&A3), dA23);
        dA23 = __hfma2(hx2, *reinterpret_cast<__half2*>(&A5), dA23);
        dA23 = __hfma2(hx3, *reinterpret_cast<__half2*>(&A7), dA23);

        // x-dot row B (y-row 2lx+1)
        __half2 dB01 = __hmul2(hx0, *reinterpret_cast<__half2*>(&B0));
        dB01 = __hfma2(hx1, *reinterpret_cast<__half2*>(&B2), dB01);
        dB01 = __hfma2(hx2, *reinterpret_cast<__half2*>(&B4), dB01);
        dB01 = __hfma2(hx3, *reinterpret_cast<__half2*>(&B6), dB01);
        __half2 dB23 = __hmul2(hx0, *reinterpret_cast<__half2*>(&B1));
        dB23 = __hfma2(hx1, *reinterpret_cast<__half2*>(&B3), dB23);
        dB23 = __hfma2(hx2, *reinterpret_cast<__half2*>(&B5), dB23);
        dB23 = __hfma2(hx3, *reinterpret_cast<__half2*>(&B7), dB23);

        // y-combine (fp16)
        __half2 e01 = __hmul2(hyA, dA01);
        e01 = __hfma2(hyB, dB01, e01);
        __half2 e23 = __hmul2(hyA, dA23);
        e23 = __hfma2(hyB, dB23, e23);

        // z-accumulate (f32)
        float wz = czv[zi];
        float2 f01 = __half22float2(e01);
        float2 f23 = __half22float2(e23);
        a0 = fmaf(wz, f01.x, a0);
        a1 = fmaf(wz, f01.y, a1);
        a2 = fmaf(wz, f23.x, a2);
        a3 = fmaf(wz, f23.y, a3);
    }

    // pair-reduce (partner lane = lx^1)
    a0 += __shfl_xor_sync(0xffffffffu, a0, 1);
    a1 += __shfl_xor_sync(0xffffffffu, a1, 1);
    a2 += __shfl_xor_sync(0xffffffffu, a2, 1);
    a3 += __shfl_xor_sync(0xffffffffu, a3, 1);

    if (lx == 0)
        reinterpret_cast<float4*>(out)[p] = make_float4(a0, a1, a2, a3);
}

// ---------------------------------------------------------------------------
extern "C" void kernel_launch(void* const* d_in, const int* in_sizes, int n_in,
                              void* d_out, int out_size) {
    const float* coords = (const float*)d_in[0];  // [N,3] f32
    const float* knots  = (const float*)d_in[1];  // [64,64,64,4] f32
    float* out          = (float*)d_out;          // [N,4] f32

    int n = in_sizes[0] / 3;

    int prep_threads = NTILE * 4;
    k_prep<<<(prep_threads + 255) / 256, 256>>>(knots);

    long long lanes = 2LL * n;              // 2 lanes per point
    k_main<<<(int)((lanes + 127) / 128), 128>>>(coords, out, n);
}

// round 9
// speedup vs baseline: 1.2609x; 1.2609x over previous
#include <cuda_runtime.h>
#include <cuda_fp16.h>

#define GSZ 64
#define NTILE (GSZ * GSZ * GSZ)   // 262144 tiles

// All-origins tile buffer: tile (z, y0, x0) holds the 4x4 (y,x) patch of
// cells (z, y0..y0+3, x0..x0+3), 4 channels, fp16 -> 16 cells * 8B = 128B
// = one cache line. 32 MB (L2-resident).
// uint4 j (j=0..7) holds cells 2j, 2j+1 (cell index c = dy*4+dx).
// Cell = {half2(ch0,ch1), half2(ch2,ch3)}.
__device__ uint4 g_tiles[NTILE * 8];

// ---------------------------------------------------------------------------
// Prep: one thread per (tile, dy). Tiles with x0>60 or y0>60 are never read
// by k_main (base indices clamped to [1,61] there), so clamp only the READ
// base; contents just need to be deterministic.
// ---------------------------------------------------------------------------
__global__ void __launch_bounds__(256) k_prep(const float* __restrict__ knots)
{
    int tid = blockIdx.x * 256 + threadIdx.x;     // NTILE*4 threads
    int t  = tid >> 2;
    int dy = tid & 3;
    if (t >= NTILE) return;

    int z  = t >> 12;
    int y0 = (t >> 6) & 63;
    int x0 = t & 63;
    int y  = min(y0, GSZ - 4) + dy;     // in-bounds
    int xc = min(x0, GSZ - 4);          // contiguous 64B read

    const float4* src = reinterpret_cast<const float4*>(knots)
                      + (z * GSZ + y) * GSZ + xc;

    float4 k0 = __ldg(src + 0);
    float4 k1 = __ldg(src + 1);
    float4 k2 = __ldg(src + 2);
    float4 k3 = __ldg(src + 3);

    uint4 o0, o1;
    __half2 h;
    h = __floats2half2_rn(k0.x, k0.y); o0.x = *reinterpret_cast<unsigned*>(&h);
    h = __floats2half2_rn(k0.z, k0.w); o0.y = *reinterpret_cast<unsigned*>(&h);
    h = __floats2half2_rn(k1.x, k1.y); o0.z = *reinterpret_cast<unsigned*>(&h);
    h = __floats2half2_rn(k1.z, k1.w); o0.w = *reinterpret_cast<unsigned*>(&h);
    h = __floats2half2_rn(k2.x, k2.y); o1.x = *reinterpret_cast<unsigned*>(&h);
    h = __floats2half2_rn(k2.z, k2.w); o1.y = *reinterpret_cast<unsigned*>(&h);
    h = __floats2half2_rn(k3.x, k3.y); o1.z = *reinterpret_cast<unsigned*>(&h);
    h = __floats2half2_rn(k3.z, k3.w); o1.w = *reinterpret_cast<unsigned*>(&h);

    g_tiles[t * 8 + dy * 2 + 0] = o0;
    g_tiles[t * 8 + dy * 2 + 1] = o1;
}

// ---------------------------------------------------------------------------
// Load one 32B tile row slice (LDG.256) into 8 named registers.
// ---------------------------------------------------------------------------
#define LDG256(r, ptr)                                                        \
    asm("ld.global.nc.v8.b32 {%0,%1,%2,%3,%4,%5,%6,%7}, [%8];"                \
        : "=r"(r##0), "=r"(r##1), "=r"(r##2), "=r"(r##3),                     \
          "=r"(r##4), "=r"(r##5), "=r"(r##6), "=r"(r##7)                      \
        : "l"(ptr))

// fp16 x-dot over 4 cells + f32 accumulate for one z-slice held in regs r0..r7
#define CONSUME(r, wz)                                                        \
    do {                                                                      \
        __half2 d01 = __hmul2(hx0, *reinterpret_cast<__half2*>(&r##0));       \
        d01 = __hfma2(hx1, *reinterpret_cast<__half2*>(&r##2), d01);          \
        d01 = __hfma2(hx2, *reinterpret_cast<__half2*>(&r##4), d01);          \
        d01 = __hfma2(hx3, *reinterpret_cast<__half2*>(&r##6), d01);          \
        __half2 d23 = __hmul2(hx0, *reinterpret_cast<__half2*>(&r##1));       \
        d23 = __hfma2(hx1, *reinterpret_cast<__half2*>(&r##3), d23);          \
        d23 = __hfma2(hx2, *reinterpret_cast<__half2*>(&r##5), d23);          \
        d23 = __hfma2(hx3, *reinterpret_cast<__half2*>(&r##7), d23);          \
        float2 f01 = __half22float2(d01);                                     \
        float2 f23 = __half22float2(d23);                                     \
        a0 = fmaf(wz, f01.x, a0);                                             \
        a1 = fmaf(wz, f01.y, a1);                                             \
        a2 = fmaf(wz, f23.x, a2);                                             \
        a3 = fmaf(wz, f23.y, a3);                                             \
    } while (0)

// ---------------------------------------------------------------------------
// Main: quad mapping (lane lx owns y-row dy=lx; one LDG.256 per z covers the
// whole 128B tile line per warp instruction -> 4 L1 wavefronts per point).
// z-loads software-pipelined at depth 2 (two 8-reg buffers, WAR reuse) so
// two loads are always in flight per lane instead of ptxas' serialized one.
// ---------------------------------------------------------------------------
__global__ void __launch_bounds__(256) k_main(const float* __restrict__ coords,
                                              float* __restrict__ out,
                                              int n)
{
    int tid = blockIdx.x * 256 + threadIdx.x;
    int p  = tid >> 2;
    int lx = tid & 3;        // = y-tap dy of this lane
    if (p >= n) return;

    float zc = __ldg(&coords[p * 3 + 0]);
    float yc = __ldg(&coords[p * 3 + 1]);
    float xc = __ldg(&coords[p * 3 + 2]);

    float fz = floorf(zc), fy = floorf(yc), fx = floorf(xc);
    int iz = (int)fz, iy = (int)fy, ix = (int)fx;
    float sz = zc - fz, sy = yc - fy, sx = xc - fx;
    iz = min(max(iz, 1), GSZ - 3);
    iy = min(max(iy, 1), GSZ - 3);
    ix = min(max(ix, 1), GSZ - 3);

    // lane's 32B slice (its y-row) of tile (z, iy-1, ix-1)
    const uint4* tbase = g_tiles
        + (size_t)(((iz - 1) * GSZ + (iy - 1)) * GSZ + (ix - 1)) * 8 + lx * 2;
    const size_t zstep = (size_t)(GSZ * GSZ * 8);

    // Kick off first two z-loads before computing the basis.
    unsigned A0, A1, A2, A3, A4, A5, A6, A7;
    unsigned B0, B1, B2, B3, B4, B5, B6, B7;
    LDG256(A, reinterpret_cast<const unsigned*>(tbase));
    LDG256(B, reinterpret_cast<const unsigned*>(tbase + zstep));

    // z basis (f32)
    float cz0 = sz * (-0.5f + sz * (1.0f - 0.5f * sz));
    float cz1 = 1.0f + sz * sz * (-2.5f + 1.5f * sz);
    float cz2 = sz * (0.5f + sz * (2.0f - 1.5f * sz));
    float cz3 = sz * sz * (0.5f * sz - 0.5f);

    // y: this lane needs only tap lx (f32, folded into wz)
    float cyl;
    {
        float c0 = sy * (-0.5f + sy * (1.0f - 0.5f * sy));
        float c1 = 1.0f + sy * sy * (-2.5f + 1.5f * sy);
        float c2 = sy * (0.5f + sy * (2.0f - 1.5f * sy));
        float c3 = sy * sy * (0.5f * sy - 0.5f);
        float ca = (lx & 1) ? c1 : c0;
        float cb = (lx & 1) ? c3 : c2;
        cyl = (lx & 2) ? cb : ca;
    }

    // x basis as broadcast half2
    __half2 hx0, hx1, hx2, hx3;
    {
        float c0 = sx * (-0.5f + sx * (1.0f - 0.5f * sx));
        float c1 = 1.0f + sx * sx * (-2.5f + 1.5f * sx);
        float c2 = sx * (0.5f + sx * (2.0f - 1.5f * sx));
        float c3 = sx * sx * (0.5f * sx - 0.5f);
        hx0 = __float2half2_rn(c0);
        hx1 = __float2half2_rn(c1);
        hx2 = __float2half2_rn(c2);
        hx3 = __float2half2_rn(c3);
    }

    float a0 = 0.f, a1 = 0.f, a2 = 0.f, a3 = 0.f;

    // z0: consume A, then refill A with z2
    CONSUME(A, cz0 * cyl);
    LDG256(A, reinterpret_cast<const unsigned*>(tbase + 2 * zstep));
    // z1: consume B, then refill B with z3
    CONSUME(B, cz1 * cyl);
    LDG256(B, reinterpret_cast<const unsigned*>(tbase + 3 * zstep));
    // z2, z3
    CONSUME(A, cz2 * cyl);
    CONSUME(B, cz3 * cyl);

    // quad-reduce (y-taps)
#pragma unroll
    for (int d = 1; d < 4; d <<= 1) {
        a0 += __shfl_xor_sync(0xffffffffu, a0, d);
        a1 += __shfl_xor_sync(0xffffffffu, a1, d);
        a2 += __shfl_xor_sync(0xffffffffu, a2, d);
        a3 += __shfl_xor_sync(0xffffffffu, a3, d);
    }

    if (lx == 0)
        reinterpret_cast<float4*>(out)[p] = make_float4(a0, a1, a2, a3);
}

// ---------------------------------------------------------------------------
extern "C" void kernel_launch(void* const* d_in, const int* in_sizes, int n_in,
                              void* d_out, int out_size) {
    const float* coords = (const float*)d_in[0];  // [N,3] f32
    const float* knots  = (const float*)d_in[1];  // [64,64,64,4] f32
    float* out          = (float*)d_out;          // [N,4] f32

    int n = in_sizes[0] / 3;

    int prep_threads = NTILE * 4;
    k_prep<<<(prep_threads + 255) / 256, 256>>>(knots);

    long long lanes = 4LL * n;              // quad mapping
    k_main<<<(int)((lanes + 255) / 256), 256>>>(coords, out, n);
}

// round 10
// speedup vs baseline: 1.2617x; 1.0007x over previous
#include <cuda_runtime.h>
#include <cuda_fp16.h>

#define GSZ 64
#define NTILE (GSZ * GSZ * GSZ)   // 262144 tiles

// All-origins tile buffer: tile (z, y0, x0) holds the 4x4 (y,x) patch of
// cells (z, y0..y0+3, x0..x0+3), 4 channels, fp16 -> 16 cells * 8B = 128B
// = one cache line. 32 MB (L2-resident).
// uint4 j (j=0..7) holds cells 2j, 2j+1 (cell index c = dy*4+dx).
// Cell = {half2(ch0,ch1), half2(ch2,ch3)}.
__device__ uint4 g_tiles[NTILE * 8];

// ---------------------------------------------------------------------------
// Prep: one thread per (tile, dy). Tiles with x0>60 or y0>60 are never read
// by k_main (base indices clamped to [1,61] there), so clamp only the READ
// base; contents just need to be deterministic.
// ---------------------------------------------------------------------------
__global__ void __launch_bounds__(256) k_prep(const float* __restrict__ knots)
{
    int tid = blockIdx.x * 256 + threadIdx.x;     // NTILE*4 threads
    int t  = tid >> 2;
    int dy = tid & 3;
    if (t >= NTILE) return;

    int z  = t >> 12;
    int y0 = (t >> 6) & 63;
    int x0 = t & 63;
    int y  = min(y0, GSZ - 4) + dy;     // in-bounds
    int xc = min(x0, GSZ - 4);          // contiguous 64B read

    const float4* src = reinterpret_cast<const float4*>(knots)
                      + (z * GSZ + y) * GSZ + xc;

    float4 k0 = __ldg(src + 0);
    float4 k1 = __ldg(src + 1);
    float4 k2 = __ldg(src + 2);
    float4 k3 = __ldg(src + 3);

    uint4 o0, o1;
    __half2 h;
    h = __floats2half2_rn(k0.x, k0.y); o0.x = *reinterpret_cast<unsigned*>(&h);
    h = __floats2half2_rn(k0.z, k0.w); o0.y = *reinterpret_cast<unsigned*>(&h);
    h = __floats2half2_rn(k1.x, k1.y); o0.z = *reinterpret_cast<unsigned*>(&h);
    h = __floats2half2_rn(k1.z, k1.w); o0.w = *reinterpret_cast<unsigned*>(&h);
    h = __floats2half2_rn(k2.x, k2.y); o1.x = *reinterpret_cast<unsigned*>(&h);
    h = __floats2half2_rn(k2.z, k2.w); o1.y = *reinterpret_cast<unsigned*>(&h);
    h = __floats2half2_rn(k3.x, k3.y); o1.z = *reinterpret_cast<unsigned*>(&h);
    h = __floats2half2_rn(k3.z, k3.w); o1.w = *reinterpret_cast<unsigned*>(&h);

    g_tiles[t * 8 + dy * 2 + 0] = o0;
    g_tiles[t * 8 + dy * 2 + 1] = o1;
}

// ---------------------------------------------------------------------------
// Load one 32B tile row slice (LDG.256) into 8 named registers.
// ---------------------------------------------------------------------------
#define LDG256(r, ptr)                                                        \
    asm("ld.global.nc.v8.b32 {%0,%1,%2,%3,%4,%5,%6,%7}, [%8];"                \
        : "=r"(r##0), "=r"(r##1), "=r"(r##2), "=r"(r##3),                     \
          "=r"(r##4), "=r"(r##5), "=r"(r##6), "=r"(r##7)                      \
        : "l"(ptr))

// fp16 x-dot over 4 cells + f32 accumulate for one z-slice held in regs r0..r7
#define CONSUME(r, wz)                                                        \
    do {                                                                      \
        __half2 d01 = __hmul2(hx0, *reinterpret_cast<__half2*>(&r##0));       \
        d01 = __hfma2(hx1, *reinterpret_cast<__half2*>(&r##2), d01);          \
        d01 = __hfma2(hx2, *reinterpret_cast<__half2*>(&r##4), d01);          \
        d01 = __hfma2(hx3, *reinterpret_cast<__half2*>(&r##6), d01);          \
        __half2 d23 = __hmul2(hx0, *reinterpret_cast<__half2*>(&r##1));       \
        d23 = __hfma2(hx1, *reinterpret_cast<__half2*>(&r##3), d23);          \
        d23 = __hfma2(hx2, *reinterpret_cast<__half2*>(&r##5), d23);          \
        d23 = __hfma2(hx3, *reinterpret_cast<__half2*>(&r##7), d23);          \
        float2 f01 = __half22float2(d01);                                     \
        float2 f23 = __half22float2(d23);                                     \
        a0 = fmaf(wz, f01.x, a0);                                             \
        a1 = fmaf(wz, f01.y, a1);                                             \
        a2 = fmaf(wz, f23.x, a2);                                             \
        a3 = fmaf(wz, f23.y, a3);                                             \
    } while (0)

// ---------------------------------------------------------------------------
// Main: quad mapping (lane lx owns y-row dy=lx; one LDG.256 per z covers the
// whole 128B tile line per warp instruction -> 4 L1 wavefronts per point).
// z-loads software-pipelined at depth 2 (two 8-reg buffers, WAR reuse) so
// two loads are always in flight per lane instead of ptxas' serialized one.
// ---------------------------------------------------------------------------
__global__ void __launch_bounds__(256) k_main(const float* __restrict__ coords,
                                              float* __restrict__ out,
                                              int n)
{
    int tid = blockIdx.x * 256 + threadIdx.x;
    int p  = tid >> 2;
    int lx = tid & 3;        // = y-tap dy of this lane
    if (p >= n) return;

    float zc = __ldg(&coords[p * 3 + 0]);
    float yc = __ldg(&coords[p * 3 + 1]);
    float xc = __ldg(&coords[p * 3 + 2]);

    float fz = floorf(zc), fy = floorf(yc), fx = floorf(xc);
    int iz = (int)fz, iy = (int)fy, ix = (int)fx;
    float sz = zc - fz, sy = yc - fy, sx = xc - fx;
    iz = min(max(iz, 1), GSZ - 3);
    iy = min(max(iy, 1), GSZ - 3);
    ix = min(max(ix, 1), GSZ - 3);

    // lane's 32B slice (its y-row) of tile (z, iy-1, ix-1)
    const uint4* tbase = g_tiles
        + (size_t)(((iz - 1) * GSZ + (iy - 1)) * GSZ + (ix - 1)) * 8 + lx * 2;
    const size_t zstep = (size_t)(GSZ * GSZ * 8);

    // Kick off first two z-loads before computing the basis.
    unsigned A0, A1, A2, A3, A4, A5, A6, A7;
    unsigned B0, B1, B2, B3, B4, B5, B6, B7;
    LDG256(A, reinterpret_cast<const unsigned*>(tbase));
    LDG256(B, reinterpret_cast<const unsigned*>(tbase + zstep));

    // z basis (f32)
    float cz0 = sz * (-0.5f + sz * (1.0f - 0.5f * sz));
    float cz1 = 1.0f + sz * sz * (-2.5f + 1.5f * sz);
    float cz2 = sz * (0.5f + sz * (2.0f - 1.5f * sz));
    float cz3 = sz * sz * (0.5f * sz - 0.5f);

    // y: this lane needs only tap lx (f32, folded into wz)
    float cyl;
    {
        float c0 = sy * (-0.5f + sy * (1.0f - 0.5f * sy));
        float c1 = 1.0f + sy * sy * (-2.5f + 1.5f * sy);
        float c2 = sy * (0.5f + sy * (2.0f - 1.5f * sy));
        float c3 = sy * sy * (0.5f * sy - 0.5f);
        float ca = (lx & 1) ? c1 : c0;
        float cb = (lx & 1) ? c3 : c2;
        cyl = (lx & 2) ? cb : ca;
    }

    // x basis as broadcast half2
    __half2 hx0, hx1, hx2, hx3;
    {
        float c0 = sx * (-0.5f + sx * (1.0f - 0.5f * sx));
        float c1 = 1.0f + sx * sx * (-2.5f + 1.5f * sx);
        float c2 = sx * (0.5f + sx * (2.0f - 1.5f * sx));
        float c3 = sx * sx * (0.5f * sx - 0.5f);
        hx0 = __float2half2_rn(c0);
        hx1 = __float2half2_rn(c1);
        hx2 = __float2half2_rn(c2);
        hx3 = __float2half2_rn(c3);
    }

    float a0 = 0.f, a1 = 0.f, a2 = 0.f, a3 = 0.f;

    // z0: consume A, then refill A with z2
    CONSUME(A, cz0 * cyl);
    LDG256(A, reinterpret_cast<const unsigned*>(tbase + 2 * zstep));
    // z1: consume B, then refill B with z3
    CONSUME(B, cz1 * cyl);
    LDG256(B, reinterpret_cast<const unsigned*>(tbase + 3 * zstep));
    // z2, z3
    CONSUME(A, cz2 * cyl);
    CONSUME(B, cz3 * cyl);

    // quad-reduce (y-taps)
#pragma unroll
    for (int d = 1; d < 4; d <<= 1) {
        a0 += __shfl_xor_sync(0xffffffffu, a0, d);
        a1 += __shfl_xor_sync(0xffffffffu, a1, d);
        a2 += __shfl_xor_sync(0xffffffffu, a2, d);
        a3 += __shfl_xor_sync(0xffffffffu, a3, d);
    }

    if (lx == 0)
        reinterpret_cast<float4*>(out)[p] = make_float4(a0, a1, a2, a3);
}

// ---------------------------------------------------------------------------
extern "C" void kernel_launch(void* const* d_in, const int* in_sizes, int n_in,
                              void* d_out, int out_size) {
    const float* coords = (const float*)d_in[0];  // [N,3] f32
    const float* knots  = (const float*)d_in[1];  // [64,64,64,4] f32
    float* out          = (float*)d_out;          // [N,4] f32

    int n = in_sizes[0] / 3;

    int prep_threads = NTILE * 4;
    k_prep<<<(prep_threads + 255) / 256, 256>>>(knots);

    long long lanes = 4LL * n;              // quad mapping
    k_main<<<(int)((lanes + 255) / 256), 256>>>(coords, out, n);
}

// round 11
// speedup vs baseline: 1.3810x; 1.0945x over previous
#include <cuda_runtime.h>
#include <cuda_fp16.h>

#define GSZ 64
#define NTILE (GSZ * GSZ * GSZ)   // 262144 tiles

// All-origins tile buffer: tile (z, y0, x0) holds the 4x4 (y,x) patch of
// cells (z, y0..y0+3, x0..x0+3), 4 channels, fp16 -> 16 cells * 8B = 128B
// = one cache line. 32 MB (L2-resident).
// uint4 j (j=0..7) holds cells 2j, 2j+1 (cell index c = dy*4+dx).
// Cell = {half2(ch0,ch1), half2(ch2,ch3)}.
__device__ uint4 g_tiles[NTILE * 8];

// ---------------------------------------------------------------------------
// Prep (slab form): one block per (z, y0). The block loads the 4 source rows
// ONCE (4KB, coalesced LDG.128, one cell per thread), converts each cell to
// fp16 exactly once, stages in padded smem, then writes all 64 tiles of the
// slab (512 uint4 = 8KB) with fully coalesced STG.128.
// Clamps reproduce the previous per-tile prep bit-exactly:
//   row  y = min(y0,60)+dy ; cells x = min(x0,60)+dx.
// Tiles with y0>60 / x0>60 are never read by k_main (deterministic filler).
// ---------------------------------------------------------------------------
__global__ void __launch_bounds__(256) k_prep(const float* __restrict__ knots)
{
    __shared__ uint2 srow[4][GSZ + 1];   // [dy][x] cell (2x half2), +1 pad

    int z  = blockIdx.x >> 6;
    int y0 = blockIdx.x & 63;
    int t  = threadIdx.x;

    // Load + convert phase: thread t -> cell (dy = t>>6, x = t&63)
    {
        int dy = t >> 6;
        int x  = t & 63;
        int yr = min(y0, GSZ - 4) + dy;
        float4 k = __ldg(reinterpret_cast<const float4*>(knots)
                         + (z * GSZ + yr) * GSZ + x);
        __half2 h0 = __floats2half2_rn(k.x, k.y);
        __half2 h1 = __floats2half2_rn(k.z, k.w);
        uint2 cell;
        cell.x = *reinterpret_cast<unsigned*>(&h0);
        cell.y = *reinterpret_cast<unsigned*>(&h1);
        srow[dy][x] = cell;
    }
    __syncthreads();

    // Write phase: 512 uint4 outputs per block; thread t writes o = t, t+256.
    // o -> tile x0 = o>>3, slot j = o&7 (dy = j>>1, dx-pair q = j&1).
    size_t base = (size_t)((z * GSZ + y0) * GSZ) * 8;   // uint4 idx of (z,y0,0)
#pragma unroll
    for (int r = 0; r < 2; r++) {
        int o   = t + r * 256;
        int x0  = o >> 3;
        int j   = o & 7;
        int dyo = j >> 1;
        int q   = j & 1;
        int xr  = min(x0, GSZ - 4) + 2 * q;
        uint2 c0 = srow[dyo][xr];
        uint2 c1 = srow[dyo][xr + 1];
        g_tiles[base + o] = make_uint4(c0.x, c0.y, c1.x, c1.y);
    }
}

// ---------------------------------------------------------------------------
// Load one 32B tile row slice (LDG.256) into 8 named registers.
// ---------------------------------------------------------------------------
#define LDG256(r, ptr)                                                        \
    asm("ld.global.nc.v8.b32 {%0,%1,%2,%3,%4,%5,%6,%7}, [%8];"                \
        : "=r"(r##0), "=r"(r##1), "=r"(r##2), "=r"(r##3),                     \
          "=r"(r##4), "=r"(r##5), "=r"(r##6), "=r"(r##7)                      \
        : "l"(ptr))

// fp16 x-dot over 4 cells + f32 accumulate for one z-slice held in regs r0..r7
#define CONSUME(r, wz)                                                        \
    do {                                                                      \
        __half2 d01 = __hmul2(hx0, *reinterpret_cast<__half2*>(&r##0));       \
        d01 = __hfma2(hx1, *reinterpret_cast<__half2*>(&r##2), d01);          \
        d01 = __hfma2(hx2, *reinterpret_cast<__half2*>(&r##4), d01);          \
        d01 = __hfma2(hx3, *reinterpret_cast<__half2*>(&r##6), d01);          \
        __half2 d23 = __hmul2(hx0, *reinterpret_cast<__half2*>(&r##1));       \
        d23 = __hfma2(hx1, *reinterpret_cast<__half2*>(&r##3), d23);          \
        d23 = __hfma2(hx2, *reinterpret_cast<__half2*>(&r##5), d23);          \
        d23 = __hfma2(hx3, *reinterpret_cast<__half2*>(&r##7), d23);          \
        float2 f01 = __half22float2(d01);                                     \
        float2 f23 = __half22float2(d23);                                     \
        a0 = fmaf(wz, f01.x, a0);                                             \
        a1 = fmaf(wz, f01.y, a1);                                             \
        a2 = fmaf(wz, f23.x, a2);                                             \
        a3 = fmaf(wz, f23.y, a3);                                             \
    } while (0)

// ---------------------------------------------------------------------------
// Main (unchanged from best kernel): quad mapping, lane lx owns y-row dy=lx;
// one LDG.256 per z covers the whole 128B tile line per warp instruction
// -> 4 L1 wavefronts per point. Depth-2 z-load pipeline.
// ---------------------------------------------------------------------------
__global__ void __launch_bounds__(256) k_main(const float* __restrict__ coords,
                                              float* __restrict__ out,
                                              int n)
{
    int tid = blockIdx.x * 256 + threadIdx.x;
    int p  = tid >> 2;
    int lx = tid & 3;        // = y-tap dy of this lane
    if (p >= n) return;

    float zc = __ldg(&coords[p * 3 + 0]);
    float yc = __ldg(&coords[p * 3 + 1]);
    float xc = __ldg(&coords[p * 3 + 2]);

    float fz = floorf(zc), fy = floorf(yc), fx = floorf(xc);
    int iz = (int)fz, iy = (int)fy, ix = (int)fx;
    float sz = zc - fz, sy = yc - fy, sx = xc - fx;
    iz = min(max(iz, 1), GSZ - 3);
    iy = min(max(iy, 1), GSZ - 3);
    ix = min(max(ix, 1), GSZ - 3);

    // lane's 32B slice (its y-row) of tile (z, iy-1, ix-1)
    const uint4* tbase = g_tiles
        + (size_t)(((iz - 1) * GSZ + (iy - 1)) * GSZ + (ix - 1)) * 8 + lx * 2;
    const size_t zstep = (size_t)(GSZ * GSZ * 8);

    // Kick off first two z-loads before computing the basis.
    unsigned A0, A1, A2, A3, A4, A5, A6, A7;
    unsigned B0, B1, B2, B3, B4, B5, B6, B7;
    LDG256(A, reinterpret_cast<const unsigned*>(tbase));
    LDG256(B, reinterpret_cast<const unsigned*>(tbase + zstep));

    // z basis (f32)
    float cz0 = sz * (-0.5f + sz * (1.0f - 0.5f * sz));
    float cz1 = 1.0f + sz * sz * (-2.5f + 1.5f * sz);
    float cz2 = sz * (0.5f + sz * (2.0f - 1.5f * sz));
    float cz3 = sz * sz * (0.5f * sz - 0.5f);

    // y: this lane needs only tap lx (f32, folded into wz)
    float cyl;
    {
        float c0 = sy * (-0.5f + sy * (1.0f - 0.5f * sy));
        float c1 = 1.0f + sy * sy * (-2.5f + 1.5f * sy);
        float c2 = sy * (0.5f + sy * (2.0f - 1.5f * sy));
        float c3 = sy * sy * (0.5f * sy - 0.5f);
        float ca = (lx & 1) ? c1 : c0;
        float cb = (lx & 1) ? c3 : c2;
        cyl = (lx & 2) ? cb : ca;
    }

    // x basis as broadcast half2
    __half2 hx0, hx1, hx2, hx3;
    {
        float c0 = sx * (-0.5f + sx * (1.0f - 0.5f * sx));
        float c1 = 1.0f + sx * sx * (-2.5f + 1.5f * sx);
        float c2 = sx * (0.5f + sx * (2.0f - 1.5f * sx));
        float c3 = sx * sx * (0.5f * sx - 0.5f);
        hx0 = __float2half2_rn(c0);
        hx1 = __float2half2_rn(c1);
        hx2 = __float2half2_rn(c2);
        hx3 = __float2half2_rn(c3);
    }

    float a0 = 0.f, a1 = 0.f, a2 = 0.f, a3 = 0.f;

    // z0: consume A, then refill A with z2
    CONSUME(A, cz0 * cyl);
    LDG256(A, reinterpret_cast<const unsigned*>(tbase + 2 * zstep));
    // z1: consume B, then refill B with z3
    CONSUME(B, cz1 * cyl);
    LDG256(B, reinterpret_cast<const unsigned*>(tbase + 3 * zstep));
    // z2, z3
    CONSUME(A, cz2 * cyl);
    CONSUME(B, cz3 * cyl);

    // quad-reduce (y-taps)
#pragma unroll
    for (int d = 1; d < 4; d <<= 1) {
        a0 += __shfl_xor_sync(0xffffffffu, a0, d);
        a1 += __shfl_xor_sync(0xffffffffu, a1, d);
        a2 += __shfl_xor_sync(0xffffffffu, a2, d);
        a3 += __shfl_xor_sync(0xffffffffu, a3, d);
    }

    if (lx == 0)
        reinterpret_cast<float4*>(out)[p] = make_float4(a0, a1, a2, a3);
}

// ---------------------------------------------------------------------------
extern "C" void kernel_launch(void* const* d_in, const int* in_sizes, int n_in,
                              void* d_out, int out_size) {
    const float* coords = (const float*)d_in[0];  // [N,3] f32
    const float* knots  = (const float*)d_in[1];  // [64,64,64,4] f32
    float* out          = (float*)d_out;          // [N,4] f32

    int n = in_sizes[0] / 3;

    k_prep<<<GSZ * GSZ, 256>>>(knots);            // one block per (z, y0)

    long long lanes = 4LL * n;                    // quad mapping
    k_main<<<(int)((lanes + 255) / 256), 256>>>(coords, out, n);
}